// round 15
// baseline (speedup 1.0000x reference)
#include <cuda_runtime.h>
#include <cuda_bf16.h>
#include <cstdint>

#define BB 32
#define TT 512
#define DD 128
#define HH 8
#define DHH 16
#define EE 8
#define DEPTH_ 4
#define FFH 512
#define NBC 55
#define NCC 8
#define INJ 440
#define KPJ 448
#define NTOK 16384
#define NASG 32768
#define SA 136   // padded bf16 row stride for mma smem tiles

typedef unsigned long long u64;

__device__ __forceinline__ u64 pk2(float x) { u64 r; asm("mov.b64 %0,{%1,%1};" : "=l"(r) : "f"(x)); return r; }
__device__ __forceinline__ float2 up2(u64 a) { float2 r; asm("mov.b64 {%0,%1},%2;" : "=f"(r.x), "=f"(r.y) : "l"(a)); return r; }
__device__ __forceinline__ u64 fma2(u64 a, u64 b, u64 c) { u64 d; asm("fma.rn.f32x2 %0,%1,%2,%3;" : "=l"(d) : "l"(a), "l"(b), "l"(c)); return d; }
__device__ __forceinline__ u64 mul2(u64 a, u64 b) { u64 d; asm("mul.rn.f32x2 %0,%1,%2;" : "=l"(d) : "l"(a), "l"(b)); return d; }
__device__ __forceinline__ u64 add2(u64 a, u64 b) { u64 d; asm("add.rn.f32x2 %0,%1,%2;" : "=l"(d) : "l"(a), "l"(b)); return d; }

#define MMA(d, a, b) \
    asm volatile("mma.sync.aligned.m16n8k16.row.col.f32.bf16.bf16.f32 " \
                 "{%0,%1,%2,%3},{%4,%5,%6,%7},{%8,%9},{%0,%1,%2,%3};" \
                 : "+f"((d)[0]), "+f"((d)[1]), "+f"((d)[2]), "+f"((d)[3]) \
                 : "r"((a)[0]), "r"((a)[1]), "r"((a)[2]), "r"((a)[3]), \
                   "r"((b)[0]), "r"((b)[1]))

union PK4 { __nv_bfloat16 b[4]; uint64_t u; };
__device__ __forceinline__ void split4(float4 v, PK4& ph, PK4& pl) {
    __nv_bfloat16 h;
    h = __float2bfloat16(v.x); ph.b[0] = h; pl.b[0] = __float2bfloat16(v.x - __bfloat162float(h));
    h = __float2bfloat16(v.y); ph.b[1] = h; pl.b[1] = __float2bfloat16(v.y - __bfloat162float(h));
    h = __float2bfloat16(v.z); ph.b[2] = h; pl.b[2] = __float2bfloat16(v.z - __bfloat162float(h));
    h = __float2bfloat16(v.w); ph.b[3] = h; pl.b[3] = __float2bfloat16(v.w - __bfloat162float(h));
}
__device__ __forceinline__ void pksplit2(float a, float b, uint32_t& h, uint32_t& l) {
    __nv_bfloat16 ah = __float2bfloat16(a), bh = __float2bfloat16(b);
    __nv_bfloat16 al = __float2bfloat16(a - __bfloat162float(ah));
    __nv_bfloat16 bl = __float2bfloat16(b - __bfloat162float(bh));
    h = (uint32_t)__bfloat16_as_ushort(ah) | ((uint32_t)__bfloat16_as_ushort(bh) << 16);
    l = (uint32_t)__bfloat16_as_ushort(al) | ((uint32_t)__bfloat16_as_ushort(bl) << 16);
}
__device__ __forceinline__ float gelu1(float x) {
    float t = tanhf(0.7978845608028654f * (x + 0.044715f * x * x * x));
    return 0.5f * x * (1.f + t);
}

// 128x128x128 bf16 warp-mma, 3 or 4 passes (full=1 adds Al*Bl)
template <int FULL>
__device__ __forceinline__ void mma_block(float (&acc)[4][4][4],
                                          const __nv_bfloat16* Ah, const __nv_bfloat16* Al,
                                          const __nv_bfloat16* Bh, const __nv_bfloat16* Bl,
                                          int mrowb, int ncolb, int lane) {
    int r_l = lane >> 2, c_l = (lane & 3) * 2;
#pragma unroll
    for (int ks = 0; ks < 8; ks++) {
        int kc = ks * 16;
        uint32_t a[4][4], b[4][2], b2[4][2];
#pragma unroll
        for (int mt = 0; mt < 4; mt++) {
            int r = mrowb + mt * 16 + r_l;
            a[mt][0] = *(const uint32_t*)(Ah + r * SA + kc + c_l);
            a[mt][1] = *(const uint32_t*)(Ah + (r + 8) * SA + kc + c_l);
            a[mt][2] = *(const uint32_t*)(Ah + r * SA + kc + c_l + 8);
            a[mt][3] = *(const uint32_t*)(Ah + (r + 8) * SA + kc + c_l + 8);
        }
#pragma unroll
        for (int ntl = 0; ntl < 4; ntl++) {
            int nn = ncolb + ntl * 8 + r_l;
            b[ntl][0] = *(const uint32_t*)(Bh + nn * SA + kc + c_l);
            b[ntl][1] = *(const uint32_t*)(Bh + nn * SA + kc + c_l + 8);
            b2[ntl][0] = *(const uint32_t*)(Bl + nn * SA + kc + c_l);
            b2[ntl][1] = *(const uint32_t*)(Bl + nn * SA + kc + c_l + 8);
        }
#pragma unroll
        for (int mt = 0; mt < 4; mt++)
#pragma unroll
            for (int ntl = 0; ntl < 4; ntl++) {
                MMA(acc[mt][ntl], a[mt], b[ntl]);
                MMA(acc[mt][ntl], a[mt], b2[ntl]);
            }
#pragma unroll
        for (int mt = 0; mt < 4; mt++) {
            int r = mrowb + mt * 16 + r_l;
            a[mt][0] = *(const uint32_t*)(Al + r * SA + kc + c_l);
            a[mt][1] = *(const uint32_t*)(Al + (r + 8) * SA + kc + c_l);
            a[mt][2] = *(const uint32_t*)(Al + r * SA + kc + c_l + 8);
            a[mt][3] = *(const uint32_t*)(Al + (r + 8) * SA + kc + c_l + 8);
        }
#pragma unroll
        for (int mt = 0; mt < 4; mt++)
#pragma unroll
            for (int ntl = 0; ntl < 4; ntl++) {
                MMA(acc[mt][ntl], a[mt], b[ntl]);
                if (FULL) MMA(acc[mt][ntl], a[mt], b2[ntl]);
            }
    }
}

// ---------------- scratch ----------------
__device__ float g_h[NTOK * DD];
__device__ float g_z[NTOK * DD];
__device__ float g_qkv[NTOK * 3 * DD];
__device__ float g_o[NTOK * DD];
__device__ float g_y[NASG * DD];
__device__ float g_blockSumP[512 * EE];
__device__ int   g_count[EE];
__device__ int   g_base[EE];
__device__ int   g_cursor[EE];
__device__ int   g_tok[NASG];
__device__ int   g_tope[NTOK * 2];
__device__ float g_topw[NTOK * 2];
__device__ int   g_pos[NTOK * 2];
__device__ float g_aux[1];
__device__ __nv_bfloat16 g_wqt_h[DEPTH_ * 384 * 128];
__device__ __nv_bfloat16 g_wqt_l[DEPTH_ * 384 * 128];
__device__ __nv_bfloat16 g_wot_h[DEPTH_ * 128 * 128];
__device__ __nv_bfloat16 g_wot_l[DEPTH_ * 128 * 128];
__device__ __nv_bfloat16 g_w1t_h[DEPTH_ * EE * 512 * 128];
__device__ __nv_bfloat16 g_w1t_l[DEPTH_ * EE * 512 * 128];
__device__ __nv_bfloat16 g_w2t_h[DEPTH_ * EE * 128 * 512];
__device__ __nv_bfloat16 g_w2t_l[DEPTH_ * EE * 128 * 512];
__device__ __nv_bfloat16 g_wpt_h[128 * KPJ];
__device__ __nv_bfloat16 g_wpt_l[128 * KPJ];
__device__ __nv_bfloat16 g_hid_h[(size_t)NASG * FFH];
__device__ __nv_bfloat16 g_hid_l[(size_t)NASG * FFH];

// transpose + split: src f32 [Z][R][C] -> dst bf16 [Z][C][R]
__global__ void k_tsplit(const float* __restrict__ src, int which, int R, int C) {
    __nv_bfloat16 *dh, *dl;
    if (which == 0)      { dh = g_wqt_h; dl = g_wqt_l; }
    else if (which == 1) { dh = g_wot_h; dl = g_wot_l; }
    else if (which == 2) { dh = g_w1t_h; dl = g_w1t_l; }
    else                 { dh = g_w2t_h; dl = g_w2t_l; }
    __shared__ float t[32][33];
    int z = blockIdx.z;
    int r0 = blockIdx.y * 32, c0 = blockIdx.x * 32;
    const float* s = src + (size_t)z * R * C;
    int tx = threadIdx.x & 31, ty = threadIdx.x >> 5;
#pragma unroll
    for (int i = 0; i < 32; i += 8) t[ty + i][tx] = s[(size_t)(r0 + ty + i) * C + c0 + tx];
    __syncthreads();
    __nv_bfloat16* ph = dh + (size_t)z * R * C;
    __nv_bfloat16* pl = dl + (size_t)z * R * C;
#pragma unroll
    for (int i = 0; i < 32; i += 8) {
        int c = c0 + ty + i, r = r0 + tx;
        float v = t[tx][ty + i];
        __nv_bfloat16 h = __float2bfloat16(v);
        ph[(size_t)c * R + r] = h;
        pl[(size_t)c * R + r] = __float2bfloat16(v - __bfloat162float(h));
    }
}

// proj weight: src f32 [INJ][128] -> dst bf16 [128][KPJ] zero-padded
__global__ void k_tsplit_proj(const float* __restrict__ src) {
    __shared__ float t[32][33];
    int r0 = blockIdx.y * 32, c0 = blockIdx.x * 32;
    int tx = threadIdx.x & 31, ty = threadIdx.x >> 5;
#pragma unroll
    for (int i = 0; i < 32; i += 8) {
        int r = r0 + ty + i;
        t[ty + i][tx] = (r < INJ) ? src[(size_t)r * 128 + c0 + tx] : 0.f;
    }
    __syncthreads();
#pragma unroll
    for (int i = 0; i < 32; i += 8) {
        int c = c0 + ty + i, r = r0 + tx;
        float v = t[tx][ty + i];
        __nv_bfloat16 h = __float2bfloat16(v);
        g_wpt_h[(size_t)c * KPJ + r] = h;
        g_wpt_l[(size_t)c * KPJ + r] = __float2bfloat16(v - __bfloat162float(h));
    }
}

// ---------------- MMA qkv with fused LN1: A = LN(g_h rows), loop over 3 N-tiles ----------------
__global__ __launch_bounds__(256, 1) void k_mma_qkv(int li, const float* __restrict__ bias,
                                                    const float* __restrict__ gam,
                                                    const float* __restrict__ bet) {
    int t0 = blockIdx.x * 128;
    extern __shared__ __nv_bfloat16 smbf[];
    __nv_bfloat16* sAh = smbf;
    __nv_bfloat16* sAl = smbf + 128 * SA;
    __nv_bfloat16* sBh = smbf + 2 * 128 * SA;
    __nv_bfloat16* sBl = smbf + 3 * 128 * SA;
    int tid = threadIdx.x;
    int lane = tid & 31, wid = tid >> 5;
    // fused LN1: warp wid handles rows wid*16..wid*16+15 (identical math to k_ln)
    {
        float g0 = gam[lane], g1 = gam[lane + 32], g2 = gam[lane + 64], g3 = gam[lane + 96];
        float bb0 = bet[lane], bb1 = bet[lane + 32], bb2 = bet[lane + 64], bb3 = bet[lane + 96];
#pragma unroll 1
        for (int rr = 0; rr < 16; rr++) {
            int row = wid * 16 + rr;
            const float* xr = g_h + (size_t)(t0 + row) * 128;
            float v0 = xr[lane], v1 = xr[lane + 32], v2 = xr[lane + 64], v3 = xr[lane + 96];
            float s = v0 + v1 + v2 + v3;
#pragma unroll
            for (int o = 16; o; o >>= 1) s += __shfl_xor_sync(0xffffffffu, s, o);
            float m = s * (1.0f / DD);
            float d0 = v0 - m, d1 = v1 - m, d2 = v2 - m, d3 = v3 - m;
            float q = d0 * d0 + d1 * d1 + d2 * d2 + d3 * d3;
#pragma unroll
            for (int o = 16; o; o >>= 1) q += __shfl_xor_sync(0xffffffffu, q, o);
            float rv = rsqrtf(q * (1.0f / DD) + 1e-5f);
            float z0 = d0 * rv * g0 + bb0, z1 = d1 * rv * g1 + bb1;
            float z2 = d2 * rv * g2 + bb2, z3 = d3 * rv * g3 + bb3;
            __nv_bfloat16 h;
            h = __float2bfloat16(z0); sAh[row * SA + lane] = h;
            sAl[row * SA + lane] = __float2bfloat16(z0 - __bfloat162float(h));
            h = __float2bfloat16(z1); sAh[row * SA + lane + 32] = h;
            sAl[row * SA + lane + 32] = __float2bfloat16(z1 - __bfloat162float(h));
            h = __float2bfloat16(z2); sAh[row * SA + lane + 64] = h;
            sAl[row * SA + lane + 64] = __float2bfloat16(z2 - __bfloat162float(h));
            h = __float2bfloat16(z3); sAh[row * SA + lane + 96] = h;
            sAl[row * SA + lane + 96] = __float2bfloat16(z3 - __bfloat162float(h));
        }
    }
    int mrowb = (wid >> 2) * 64, ncolb = (wid & 3) * 32;
    int r_l = lane >> 2, c_l = (lane & 3) * 2;
#pragma unroll 1
    for (int nt = 0; nt < 3; nt++) {
        const __nv_bfloat16* bh = g_wqt_h + (size_t)li * 384 * 128 + (size_t)(nt * 128) * 128;
        const __nv_bfloat16* bl = g_wqt_l + (size_t)li * 384 * 128 + (size_t)(nt * 128) * 128;
        for (int idx = tid; idx < 4096; idx += 256) {
            int r = idx >> 5, q = (idx & 31) << 2;
            *(uint64_t*)(sBh + r * SA + q) = *(const uint64_t*)(bh + (size_t)r * 128 + q);
            *(uint64_t*)(sBl + r * SA + q) = *(const uint64_t*)(bl + (size_t)r * 128 + q);
        }
        __syncthreads();
        float acc[4][4][4] = {};
        mma_block<1>(acc, sAh, sAl, sBh, sBl, mrowb, ncolb, lane);
        __syncthreads();
        const float* bp = bias + nt * 128;
#pragma unroll
        for (int mt = 0; mt < 4; mt++)
#pragma unroll
            for (int ntl = 0; ntl < 4; ntl++) {
                int row = t0 + mrowb + mt * 16 + r_l;
                int c = ncolb + ntl * 8 + c_l;
                float b0 = bp[c], b1v = bp[c + 1];
                *(float2*)(g_qkv + (size_t)row * 384 + nt * 128 + c) =
                    make_float2(acc[mt][ntl][0] + b0, acc[mt][ntl][1] + b1v);
                *(float2*)(g_qkv + (size_t)(row + 8) * 384 + nt * 128 + c) =
                    make_float2(acc[mt][ntl][2] + b0, acc[mt][ntl][3] + b1v);
            }
    }
}

// ---------------- MMA out-proj + residual ----------------
__global__ __launch_bounds__(256, 1) void k_mma_out(int li, const float* __restrict__ bias) {
    int t0 = blockIdx.x * 128;
    extern __shared__ __nv_bfloat16 smbf[];
    __nv_bfloat16* sAh = smbf;
    __nv_bfloat16* sAl = smbf + 128 * SA;
    __nv_bfloat16* sBh = smbf + 2 * 128 * SA;
    __nv_bfloat16* sBl = smbf + 3 * 128 * SA;
    int tid = threadIdx.x;
    for (int idx = tid; idx < 4096; idx += 256) {
        int r = idx >> 5, q = (idx & 31) << 2;
        float4 v = *(const float4*)(g_o + (size_t)(t0 + r) * 128 + q);
        PK4 ph, pl; split4(v, ph, pl);
        *(uint64_t*)(sAh + r * SA + q) = ph.u;
        *(uint64_t*)(sAl + r * SA + q) = pl.u;
    }
    {
        const __nv_bfloat16* bh = g_wot_h + (size_t)li * 128 * 128;
        const __nv_bfloat16* bl = g_wot_l + (size_t)li * 128 * 128;
        for (int idx = tid; idx < 4096; idx += 256) {
            int r = idx >> 5, q = (idx & 31) << 2;
            *(uint64_t*)(sBh + r * SA + q) = *(const uint64_t*)(bh + (size_t)r * 128 + q);
            *(uint64_t*)(sBl + r * SA + q) = *(const uint64_t*)(bl + (size_t)r * 128 + q);
        }
    }
    __syncthreads();
    int lane = tid & 31, wid = tid >> 5;
    int mrowb = (wid >> 2) * 64, ncolb = (wid & 3) * 32;
    float acc[4][4][4] = {};
    mma_block<1>(acc, sAh, sAl, sBh, sBl, mrowb, ncolb, lane);
    int r_l = lane >> 2, c_l = (lane & 3) * 2;
#pragma unroll
    for (int mt = 0; mt < 4; mt++)
#pragma unroll
        for (int ntl = 0; ntl < 4; ntl++) {
            int row = t0 + mrowb + mt * 16 + r_l;
            int c = ncolb + ntl * 8 + c_l;
            float b0 = bias[c], b1v = bias[c + 1];
            float2* p0 = (float2*)(g_h + (size_t)row * 128 + c);
            float2* p1 = (float2*)(g_h + (size_t)(row + 8) * 128 + c);
            float2 h0 = *p0, h1 = *p1;
            *p0 = make_float2(h0.x + acc[mt][ntl][0] + b0, h0.y + acc[mt][ntl][1] + b1v);
            *p1 = make_float2(h1.x + acc[mt][ntl][2] + b0, h1.y + acc[mt][ntl][3] + b1v);
        }
}

// ---------------- MMA input projection ----------------
__global__ __launch_bounds__(256, 1) void k_mma_proj(const float* __restrict__ x,
                                                     const float* __restrict__ bias,
                                                     const float* __restrict__ pos) {
    int t0 = blockIdx.x * 128;
    extern __shared__ __nv_bfloat16 smbf[];
    __nv_bfloat16* sAh = smbf;
    __nv_bfloat16* sAl = smbf + 128 * SA;
    __nv_bfloat16* sBh = smbf + 2 * 128 * SA;
    __nv_bfloat16* sBl = smbf + 3 * 128 * SA;
    int tid = threadIdx.x;
    int lane = tid & 31, wid = tid >> 5;
    int mrowb = (wid >> 2) * 64, ncolb = (wid & 3) * 32;
    float acc[4][4][4] = {};
#pragma unroll 1
    for (int kt = 0; kt < 4; kt++) {
        for (int idx = tid; idx < 4096; idx += 256) {
            int r = idx >> 5, q = (idx & 31) << 2;
            int tok = t0 + r;
            int b = tok >> 9, t = tok & 511;
            float4 v;
            int j0 = kt * 128 + q;
#pragma unroll
            for (int c = 0; c < 4; c++) {
                int j = j0 + c;
                float val = 0.f;
                if (j < INJ) val = x[(((size_t)(b * NBC + j / NCC) * TT + t) * NCC) + (j % NCC)];
                ((float*)&v)[c] = val;
            }
            PK4 ph, pl; split4(v, ph, pl);
            *(uint64_t*)(sAh + r * SA + q) = ph.u;
            *(uint64_t*)(sAl + r * SA + q) = pl.u;
        }
        for (int idx = tid; idx < 4096; idx += 256) {
            int r = idx >> 5, q = (idx & 31) << 2;
            *(uint64_t*)(sBh + r * SA + q) = *(const uint64_t*)(g_wpt_h + (size_t)r * KPJ + kt * 128 + q);
            *(uint64_t*)(sBl + r * SA + q) = *(const uint64_t*)(g_wpt_l + (size_t)r * KPJ + kt * 128 + q);
        }
        __syncthreads();
        mma_block<1>(acc, sAh, sAl, sBh, sBl, mrowb, ncolb, lane);
        __syncthreads();
    }
    int r_l = lane >> 2, c_l = (lane & 3) * 2;
#pragma unroll
    for (int mt = 0; mt < 4; mt++)
#pragma unroll
        for (int ntl = 0; ntl < 4; ntl++) {
            int row = t0 + mrowb + mt * 16 + r_l;
            int c = ncolb + ntl * 8 + c_l;
            float b0 = bias[c], b1v = bias[c + 1];
            int ta = row & 511, tb = (row + 8) & 511;
            float2 pA = *(const float2*)(pos + (size_t)ta * 128 + c);
            float2 pB = *(const float2*)(pos + (size_t)tb * 128 + c);
            *(float2*)(g_h + (size_t)row * 128 + c) =
                make_float2(acc[mt][ntl][0] + b0 + pA.x, acc[mt][ntl][1] + b1v + pA.y);
            *(float2*)(g_h + (size_t)(row + 8) * 128 + c) =
                make_float2(acc[mt][ntl][2] + b0 + pB.x, acc[mt][ntl][3] + b1v + pB.y);
        }
}

// ---------------- FFN GEMM1 + gelu: A gathered once, loop over 4 f-tiles, 3-pass ----------------
__global__ __launch_bounds__(256, 1) void k_ffn1(int li, const float* __restrict__ b1) {
    int e = blockIdx.y;
    int n = g_count[e];
    int start = blockIdx.x * 128;
    if (start >= n) return;
    int base = g_base[e];
    extern __shared__ __nv_bfloat16 smbf[];
    __nv_bfloat16* sAh = smbf;
    __nv_bfloat16* sAl = smbf + 128 * SA;
    __nv_bfloat16* sBh = smbf + 2 * 128 * SA;
    __nv_bfloat16* sBl = smbf + 3 * 128 * SA;
    __shared__ int toks[128];
    int tid = threadIdx.x;
    if (tid < 128) toks[tid] = (start + tid < n) ? g_tok[base + start + tid] : -1;
    __syncthreads();
    for (int idx = tid; idx < 4096; idx += 256) {
        int r = idx >> 5, q = (idx & 31) << 2;
        int tk = toks[r];
        float4 v = make_float4(0.f, 0.f, 0.f, 0.f);
        if (tk >= 0) v = *(const float4*)(g_z + (size_t)tk * 128 + q);
        PK4 ph, pl; split4(v, ph, pl);
        *(uint64_t*)(sAh + r * SA + q) = ph.u;
        *(uint64_t*)(sAl + r * SA + q) = pl.u;
    }
    int lane = tid & 31, wid = tid >> 5;
    int mrowb = (wid >> 2) * 64, ncolb = (wid & 3) * 32;
    int r_l = lane >> 2, c_l = (lane & 3) * 2;
    const __nv_bfloat16* W1h = g_w1t_h + (size_t)(li * EE + e) * 512 * 128;
    const __nv_bfloat16* W1l = g_w1t_l + (size_t)(li * EE + e) * 512 * 128;
#pragma unroll 1
    for (int nt = 0; nt < 4; nt++) {
        const __nv_bfloat16* bh = W1h + (size_t)(nt * 128) * 128;
        const __nv_bfloat16* bl = W1l + (size_t)(nt * 128) * 128;
        for (int idx = tid; idx < 4096; idx += 256) {
            int r = idx >> 5, q = (idx & 31) << 2;
            *(uint64_t*)(sBh + r * SA + q) = *(const uint64_t*)(bh + (size_t)r * 128 + q);
            *(uint64_t*)(sBl + r * SA + q) = *(const uint64_t*)(bl + (size_t)r * 128 + q);
        }
        __syncthreads();
        float acc[4][4][4] = {};
        mma_block<0>(acc, sAh, sAl, sBh, sBl, mrowb, ncolb, lane);
        __syncthreads();
        const float* b1p = b1 + e * FFH + nt * 128;
#pragma unroll
        for (int mt = 0; mt < 4; mt++)
#pragma unroll
            for (int ntl = 0; ntl < 4; ntl++) {
                int rloc = mrowb + mt * 16 + r_l;
                int f = ncolb + ntl * 8 + c_l;
                float bb0 = b1p[f], bb1 = b1p[f + 1];
                uint32_t h, l;
                if (start + rloc < n) {
                    float v0 = gelu1(acc[mt][ntl][0] + bb0);
                    float v1 = gelu1(acc[mt][ntl][1] + bb1);
                    pksplit2(v0, v1, h, l);
                    size_t o = (size_t)(base + start + rloc) * FFH + nt * 128 + f;
                    *(uint32_t*)(g_hid_h + o) = h;
                    *(uint32_t*)(g_hid_l + o) = l;
                }
                if (start + rloc + 8 < n) {
                    float v2 = gelu1(acc[mt][ntl][2] + bb0);
                    float v3 = gelu1(acc[mt][ntl][3] + bb1);
                    pksplit2(v2, v3, h, l);
                    size_t o = (size_t)(base + start + rloc + 8) * FFH + nt * 128 + f;
                    *(uint32_t*)(g_hid_h + o) = h;
                    *(uint32_t*)(g_hid_l + o) = l;
                }
            }
    }
}

// ---------------- FFN GEMM2 (3-pass) ----------------
__global__ __launch_bounds__(256, 1) void k_ffn2(int li, const float* __restrict__ b2) {
    int e = blockIdx.y;
    int n = g_count[e];
    int start = blockIdx.x * 128;
    if (start >= n) return;
    int base = g_base[e];
    extern __shared__ __nv_bfloat16 smbf[];
    __nv_bfloat16* sAh = smbf;
    __nv_bfloat16* sAl = smbf + 128 * SA;
    __nv_bfloat16* sBh = smbf + 2 * 128 * SA;
    __nv_bfloat16* sBl = smbf + 3 * 128 * SA;
    int tid = threadIdx.x;
    int lane = tid & 31, wid = tid >> 5;
    int mrowb = (wid >> 2) * 64, ncolb = (wid & 3) * 32;
    float acc[4][4][4] = {};
    const __nv_bfloat16* W2h = g_w2t_h + (size_t)(li * EE + e) * 128 * 512;
    const __nv_bfloat16* W2l = g_w2t_l + (size_t)(li * EE + e) * 128 * 512;
#pragma unroll 1
    for (int kt = 0; kt < 4; kt++) {
        for (int idx = tid; idx < 4096; idx += 256) {
            int r = idx >> 5, q = (idx & 31) << 2;
            uint64_t vh = 0, vl = 0;
            if (start + r < n) {
                size_t o = (size_t)(base + start + r) * FFH + kt * 128 + q;
                vh = *(const uint64_t*)(g_hid_h + o);
                vl = *(const uint64_t*)(g_hid_l + o);
            }
            *(uint64_t*)(sAh + r * SA + q) = vh;
            *(uint64_t*)(sAl + r * SA + q) = vl;
        }
        for (int idx = tid; idx < 4096; idx += 256) {
            int r = idx >> 5, q = (idx & 31) << 2;
            *(uint64_t*)(sBh + r * SA + q) = *(const uint64_t*)(W2h + (size_t)r * 512 + kt * 128 + q);
            *(uint64_t*)(sBl + r * SA + q) = *(const uint64_t*)(W2l + (size_t)r * 512 + kt * 128 + q);
        }
        __syncthreads();
        mma_block<0>(acc, sAh, sAl, sBh, sBl, mrowb, ncolb, lane);
        __syncthreads();
    }
    const float* b2p = b2 + e * DD;
    int r_l = lane >> 2, c_l = (lane & 3) * 2;
#pragma unroll
    for (int mt = 0; mt < 4; mt++)
#pragma unroll
        for (int ntl = 0; ntl < 4; ntl++) {
            int rloc = mrowb + mt * 16 + r_l;
            int col = ncolb + ntl * 8 + c_l;
            float b0 = b2p[col], b1v = b2p[col + 1];
            if (start + rloc < n)
                *(float2*)(g_y + (size_t)(base + start + rloc) * DD + col) =
                    make_float2(acc[mt][ntl][0] + b0, acc[mt][ntl][1] + b1v);
            if (start + rloc + 8 < n)
                *(float2*)(g_y + (size_t)(base + start + rloc + 8) * DD + col) =
                    make_float2(acc[mt][ntl][2] + b0, acc[mt][ntl][3] + b1v);
        }
}

// ---------------- LayerNorm (ln2 only) ----------------
__global__ void k_ln(const float* __restrict__ gam, const float* __restrict__ bet) {
    int warp = (blockIdx.x * blockDim.x + threadIdx.x) >> 5;
    int lane = threadIdx.x & 31;
    if (warp >= NTOK) return;
    const float* xr = g_h + warp * DD;
    float v[4];
    float s = 0.f;
#pragma unroll
    for (int j = 0; j < 4; j++) { v[j] = xr[lane + j * 32]; s += v[j]; }
#pragma unroll
    for (int o = 16; o; o >>= 1) s += __shfl_xor_sync(0xffffffffu, s, o);
    float m = s * (1.0f / DD);
    float q = 0.f;
#pragma unroll
    for (int j = 0; j < 4; j++) { float dv = v[j] - m; q += dv * dv; }
#pragma unroll
    for (int o = 16; o; o >>= 1) q += __shfl_xor_sync(0xffffffffu, q, o);
    float r = rsqrtf(q * (1.0f / DD) + 1e-5f);
#pragma unroll
    for (int j = 0; j < 4; j++) {
        int d = lane + j * 32;
        g_z[warp * DD + d] = (v[j] - m) * r * gam[d] + bet[d];
    }
}

// ---------------- attention (monolithic, round-13 verified) ----------------
__global__ __launch_bounds__(256) void k_attn() {
    extern __shared__ float sm[];
    float* Ks = sm;
    float* Vs = sm + TT * DHH;
    int b = blockIdx.x >> 3, hh = blockIdx.x & 7;
    const float* base = g_qkv + (b * TT) * 384;
    for (int idx = threadIdx.x; idx < TT * DHH; idx += 256) {
        int k = idx >> 4, d = idx & 15;
        Ks[idx] = base[k * 384 + 128 + hh * 16 + d];
        Vs[idx] = base[k * 384 + 256 + hh * 16 + d];
    }
    __syncthreads();
    int r0 = threadIdx.x, r1 = threadIdx.x + 256;
    u64 q0[8], q1[8], o0[8] = {}, o1[8] = {};
    {
        const ulonglong2* qp0 = (const ulonglong2*)(base + r0 * 384 + hh * 16);
        const ulonglong2* qp1 = (const ulonglong2*)(base + r1 * 384 + hh * 16);
        u64 sc = pk2(0.25f);
#pragma unroll
        for (int j = 0; j < 4; j++) {
            ulonglong2 t = qp0[j];
            q0[2 * j] = mul2(t.x, sc); q0[2 * j + 1] = mul2(t.y, sc);
            t = qp1[j];
            q1[2 * j] = mul2(t.x, sc); q1[2 * j + 1] = mul2(t.y, sc);
        }
    }
    float m0 = -1e30f, l0 = 0.f, m1 = -1e30f, l1 = 0.f;
#pragma unroll 1
    for (int k = 0; k < TT; k++) {
        const ulonglong2* kp = (const ulonglong2*)(Ks + k * 16);
        u64 kk[8];
#pragma unroll
        for (int j = 0; j < 4; j++) { ulonglong2 t = kp[j]; kk[2 * j] = t.x; kk[2 * j + 1] = t.y; }
        u64 sa = mul2(q0[0], kk[0]), sb = mul2(q0[1], kk[1]);
        sa = fma2(q0[2], kk[2], sa); sb = fma2(q0[3], kk[3], sb);
        sa = fma2(q0[4], kk[4], sa); sb = fma2(q0[5], kk[5], sb);
        sa = fma2(q0[6], kk[6], sa); sb = fma2(q0[7], kk[7], sb);
        float2 sr = up2(add2(sa, sb));
        float s0v = sr.x + sr.y;
        sa = mul2(q1[0], kk[0]); sb = mul2(q1[1], kk[1]);
        sa = fma2(q1[2], kk[2], sa); sb = fma2(q1[3], kk[3], sb);
        sa = fma2(q1[4], kk[4], sa); sb = fma2(q1[5], kk[5], sb);
        sa = fma2(q1[6], kk[6], sa); sb = fma2(q1[7], kk[7], sb);
        sr = up2(add2(sa, sb));
        float s1v = sr.x + sr.y;
        const ulonglong2* vp = (const ulonglong2*)(Vs + k * 16);
        u64 vv[8];
#pragma unroll
        for (int j = 0; j < 4; j++) { ulonglong2 t = vp[j]; vv[2 * j] = t.x; vv[2 * j + 1] = t.y; }
        if (s0v > m0) {
            float f = __expf(m0 - s0v);
            l0 *= f;
            u64 fp = pk2(f);
#pragma unroll
            for (int j = 0; j < 8; j++) o0[j] = mul2(o0[j], fp);
            m0 = s0v;
        }
        float p0 = __expf(s0v - m0);
        l0 += p0;
        u64 pp0 = pk2(p0);
#pragma unroll
        for (int j = 0; j < 8; j++) o0[j] = fma2(pp0, vv[j], o0[j]);
        if (s1v > m1) {
            float f = __expf(m1 - s1v);
            l1 *= f;
            u64 fp = pk2(f);
#pragma unroll
            for (int j = 0; j < 8; j++) o1[j] = mul2(o1[j], fp);
            m1 = s1v;
        }
        float p1 = __expf(s1v - m1);
        l1 += p1;
        u64 pp1 = pk2(p1);
#pragma unroll
        for (int j = 0; j < 8; j++) o1[j] = fma2(pp1, vv[j], o1[j]);
    }
    float inv0 = 1.f / l0, inv1 = 1.f / l1;
    float4* op0 = (float4*)(g_o + (b * TT + r0) * DD + hh * 16);
    float4* op1 = (float4*)(g_o + (b * TT + r1) * DD + hh * 16);
#pragma unroll
    for (int j = 0; j < 4; j++) {
        float2 a = up2(o0[2 * j]), c = up2(o0[2 * j + 1]);
        op0[j] = make_float4(a.x * inv0, a.y * inv0, c.x * inv0, c.y * inv0);
        a = up2(o1[2 * j]); c = up2(o1[2 * j + 1]);
        op1[j] = make_float4(a.x * inv1, a.y * inv1, c.x * inv1, c.y * inv1);
    }
}

// ---------------- gate / scan / assign / combine / head ----------------
__global__ void k_zero_gate() { if (threadIdx.x < EE) g_count[threadIdx.x] = 0; }

__global__ void k_gate(const float* __restrict__ gW) {
    __shared__ float zs[32 * DD];
    __shared__ float gw[DD * EE];
    __shared__ float lg[32 * EE];
    __shared__ float sp[32 * EE];
    int t0 = blockIdx.x * 32;
    for (int idx = threadIdx.x; idx < 32 * DD; idx += 256) zs[idx] = g_z[t0 * DD + idx];
    for (int idx = threadIdx.x; idx < DD * EE; idx += 256) gw[idx] = gW[idx];
    __syncthreads();
    {
        int tok = threadIdx.x >> 3, e = threadIdx.x & 7;
        float acc = 0.f;
        for (int k = 0; k < DD; k++) acc += zs[tok * DD + k] * gw[k * EE + e];
        lg[tok * EE + e] = acc;
    }
    __syncthreads();
    if (threadIdx.x < 32) {
        int tt = threadIdx.x;
        float mx = -1e30f;
#pragma unroll
        for (int j = 0; j < 8; j++) mx = fmaxf(mx, lg[tt * 8 + j]);
        float p[8];
        float s = 0.f;
#pragma unroll
        for (int j = 0; j < 8; j++) { p[j] = __expf(lg[tt * 8 + j] - mx); s += p[j]; }
        float invs = 1.f / s;
#pragma unroll
        for (int j = 0; j < 8; j++) p[j] *= invs;
        int i1 = 0; float l1 = lg[tt * 8];
        for (int j = 1; j < 8; j++) if (lg[tt * 8 + j] > l1) { l1 = lg[tt * 8 + j]; i1 = j; }
        int i2 = -1; float l2 = -1e30f;
        for (int j = 0; j < 8; j++)
            if (j != i1 && lg[tt * 8 + j] > l2) { l2 = lg[tt * 8 + j]; i2 = j; }
        float v1 = p[i1], v2 = p[i2];
        float ws = 1.f / (v1 + v2);
        int t = t0 + tt;
        g_tope[t * 2] = i1; g_tope[t * 2 + 1] = i2;
        g_topw[t * 2] = v1 * ws; g_topw[t * 2 + 1] = v2 * ws;
        atomicAdd(&g_count[i1], 1);
        atomicAdd(&g_count[i2], 1);
#pragma unroll
        for (int j = 0; j < 8; j++) sp[tt * 8 + j] = p[j];
    }
    __syncthreads();
    if (threadIdx.x < 8) {
        float s = 0.f;
        for (int tt = 0; tt < 32; tt++) s += sp[tt * 8 + threadIdx.x];
        g_blockSumP[blockIdx.x * 8 + threadIdx.x] = s;
    }
}

__global__ void k_scan_aux() {
    __shared__ float sump[8];
    int tid = threadIdx.x;
    if (tid < 8) {
        float s = 0.f;
        for (int b = 0; b < 512; b++) s += g_blockSumP[b * 8 + tid];
        sump[tid] = s;
    }
    __syncthreads();
    if (tid == 0) {
        int off = 0;
        float a = 0.f;
        for (int e = 0; e < 8; e++) {
            g_base[e] = off;
            g_cursor[e] = off;
            off += g_count[e];
            a += sump[e] * (float)g_count[e];
        }
        g_aux[0] += 8.0f * a / (16384.f * 16384.f);
    }
}

__global__ void k_assign() {
    __shared__ int cnt[8], gbase[8];
    int tid = threadIdx.x;
    if (tid < 8) cnt[tid] = 0;
    __syncthreads();
    int t = blockIdx.x * 256 + tid;
    int e0 = g_tope[t * 2], e1 = g_tope[t * 2 + 1];
    int o0 = atomicAdd(&cnt[e0], 1);
    int o1 = atomicAdd(&cnt[e1], 1);
    __syncthreads();
    if (tid < 8) gbase[tid] = atomicAdd(&g_cursor[tid], cnt[tid]);
    __syncthreads();
    int p0 = gbase[e0] + o0, p1 = gbase[e1] + o1;
    g_tok[p0] = t; g_tok[p1] = t;
    g_pos[t * 2] = p0; g_pos[t * 2 + 1] = p1;
}

__global__ void k_combine() {
    int idx = blockIdx.x * 256 + threadIdx.x;
    int t = idx >> 7, d = idx & 127;
    float w0 = g_topw[t * 2], w1v = g_topw[t * 2 + 1];
    int p0 = g_pos[t * 2], p1 = g_pos[t * 2 + 1];
    g_h[idx] += w0 * g_y[p0 * DD + d] + w1v * g_y[p1 * DD + d];
}

__global__ void k_head(const float* __restrict__ lng, const float* __restrict__ lnb,
                       const float* __restrict__ hW, const float* __restrict__ hb,
                       float* __restrict__ out, int out_size) {
    __shared__ float red[128];
    int b = blockIdx.x, d = threadIdx.x;
    float s = 0.f;
    for (int t = 0; t < TT; t++) s += g_h[(b * TT + t) * DD + d];
    float x = s * (1.f / TT);
    red[d] = x;
    __syncthreads();
    for (int o = 64; o; o >>= 1) { if (d < o) red[d] += red[d + o]; __syncthreads(); }
    float m = red[0] * (1.f / DD);
    __syncthreads();
    float dv = x - m;
    red[d] = dv * dv;
    __syncthreads();
    for (int o = 64; o; o >>= 1) { if (d < o) red[d] += red[d + o]; __syncthreads(); }
    float var = red[0] * (1.f / DD);
    __syncthreads();
    float p = dv * rsqrtf(var + 1e-5f) * lng[d] + lnb[d];
#pragma unroll 1
    for (int j = 0; j < 2; j++) {
        red[d] = p * hW[d * 2 + j];
        __syncthreads();
        for (int o = 64; o; o >>= 1) { if (d < o) red[d] += red[d + o]; __syncthreads(); }
        if (d == 0) out[b * 2 + j] = red[0] + hb[j];
        __syncthreads();
    }
    if (b == 0 && d == 0 && out_size > 64) out[64] = g_aux[0];
}

__global__ void k_zero_aux() { if (threadIdx.x == 0) g_aux[0] = 0.f; }

// ---------------- host launch ----------------
extern "C" void kernel_launch(void* const* d_in, const int* in_sizes, int n_in,
                              void* d_out, int out_size) {
    const float* x     = (const float*)d_in[0];
    const float* projW = (const float*)d_in[1];
    const float* projb = (const float*)d_in[2];
    const float* pos   = (const float*)d_in[3];
    const float* ln1g  = (const float*)d_in[4];
    const float* ln1b  = (const float*)d_in[5];
    const float* qkvW  = (const float*)d_in[6];
    const float* qkvb  = (const float*)d_in[7];
    const float* outW  = (const float*)d_in[8];
    const float* outb  = (const float*)d_in[9];
    const float* ln2g  = (const float*)d_in[10];
    const float* ln2b  = (const float*)d_in[11];
    const float* gateW = (const float*)d_in[12];
    const float* w1    = (const float*)d_in[13];
    const float* b1    = (const float*)d_in[14];
    const float* w2    = (const float*)d_in[15];
    const float* b2    = (const float*)d_in[16];
    const float* hlng  = (const float*)d_in[17];
    const float* hlnb  = (const float*)d_in[18];
    const float* hW    = (const float*)d_in[19];
    const float* hb    = (const float*)d_in[20];
    float* out = (float*)d_out;

    const int FFNS = 4 * 128 * SA * 2;   // 139264

    cudaFuncSetAttribute(k_attn, cudaFuncAttributeMaxDynamicSharedMemorySize, 65536);
    cudaFuncSetAttribute(k_ffn1, cudaFuncAttributeMaxDynamicSharedMemorySize, FFNS);
    cudaFuncSetAttribute(k_ffn2, cudaFuncAttributeMaxDynamicSharedMemorySize, FFNS);
    cudaFuncSetAttribute(k_mma_qkv, cudaFuncAttributeMaxDynamicSharedMemorySize, FFNS);
    cudaFuncSetAttribute(k_mma_out, cudaFuncAttributeMaxDynamicSharedMemorySize, FFNS);
    cudaFuncSetAttribute(k_mma_proj, cudaFuncAttributeMaxDynamicSharedMemorySize, FFNS);

    k_zero_aux<<<1, 32>>>();
    k_tsplit<<<dim3(12, 4, 4), 256>>>(qkvW, 0, 128, 384);
    k_tsplit<<<dim3(4, 4, 4), 256>>>(outW, 1, 128, 128);
    k_tsplit<<<dim3(16, 4, 32), 256>>>(w1, 2, 128, 512);
    k_tsplit<<<dim3(4, 16, 32), 256>>>(w2, 3, 512, 128);
    k_tsplit_proj<<<dim3(4, 14), 256>>>(projW);
    k_mma_proj<<<NTOK / 128, 256, FFNS>>>(x, projb, pos);

    for (int i = 0; i < DEPTH_; i++) {
        k_mma_qkv<<<NTOK / 128, 256, FFNS>>>(i, qkvb + i * 384, ln1g + i * DD, ln1b + i * DD);
        k_attn<<<BB * HH, 256, 65536>>>();
        k_mma_out<<<NTOK / 128, 256, FFNS>>>(i, outb + i * DD);
        k_ln<<<NTOK / 8, 256>>>(ln2g + i * DD, ln2b + i * DD);
        k_zero_gate<<<1, 32>>>();
        k_gate<<<NTOK / 32, 256>>>(gateW + i * DD * EE);
        k_scan_aux<<<1, 32>>>();
        k_assign<<<NTOK / 256, 256>>>();
        k_ffn1<<<dim3(128, EE), 256, FFNS>>>(i, b1 + i * EE * FFH);
        k_ffn2<<<dim3(128, EE), 256, FFNS>>>(i, b2 + i * EE * DD);
        k_combine<<<NTOK * DD / 256, 256>>>();
    }

    k_head<<<BB, 128>>>(hlng, hlnb, hW, hb, out, out_size);
}

// round 16
// speedup vs baseline: 1.6892x; 1.6892x over previous
#include <cuda_runtime.h>
#include <cuda_bf16.h>
#include <cstdint>

#define BB 32
#define TT 512
#define DD 128
#define HH 8
#define DHH 16
#define EE 8
#define DEPTH_ 4
#define FFH 512
#define NBC 55
#define NCC 8
#define INJ 440
#define KPJ 448
#define NTOK 16384
#define NASG 32768
#define SA 136   // padded bf16 row stride for mma smem tiles

typedef unsigned long long u64;

__device__ __forceinline__ u64 pk2(float x) { u64 r; asm("mov.b64 %0,{%1,%1};" : "=l"(r) : "f"(x)); return r; }
__device__ __forceinline__ float2 up2(u64 a) { float2 r; asm("mov.b64 {%0,%1},%2;" : "=f"(r.x), "=f"(r.y) : "l"(a)); return r; }
__device__ __forceinline__ u64 fma2(u64 a, u64 b, u64 c) { u64 d; asm("fma.rn.f32x2 %0,%1,%2,%3;" : "=l"(d) : "l"(a), "l"(b), "l"(c)); return d; }
__device__ __forceinline__ u64 mul2(u64 a, u64 b) { u64 d; asm("mul.rn.f32x2 %0,%1,%2;" : "=l"(d) : "l"(a), "l"(b)); return d; }
__device__ __forceinline__ u64 add2(u64 a, u64 b) { u64 d; asm("add.rn.f32x2 %0,%1,%2;" : "=l"(d) : "l"(a), "l"(b)); return d; }

#define MMA(d, a, b) \
    asm volatile("mma.sync.aligned.m16n8k16.row.col.f32.bf16.bf16.f32 " \
                 "{%0,%1,%2,%3},{%4,%5,%6,%7},{%8,%9},{%0,%1,%2,%3};" \
                 : "+f"((d)[0]), "+f"((d)[1]), "+f"((d)[2]), "+f"((d)[3]) \
                 : "r"((a)[0]), "r"((a)[1]), "r"((a)[2]), "r"((a)[3]), \
                   "r"((b)[0]), "r"((b)[1]))

union PK4 { __nv_bfloat16 b[4]; uint64_t u; };
__device__ __forceinline__ void split4(float4 v, PK4& ph, PK4& pl) {
    __nv_bfloat16 h;
    h = __float2bfloat16(v.x); ph.b[0] = h; pl.b[0] = __float2bfloat16(v.x - __bfloat162float(h));
    h = __float2bfloat16(v.y); ph.b[1] = h; pl.b[1] = __float2bfloat16(v.y - __bfloat162float(h));
    h = __float2bfloat16(v.z); ph.b[2] = h; pl.b[2] = __float2bfloat16(v.z - __bfloat162float(h));
    h = __float2bfloat16(v.w); ph.b[3] = h; pl.b[3] = __float2bfloat16(v.w - __bfloat162float(h));
}
__device__ __forceinline__ void pksplit2(float a, float b, uint32_t& h, uint32_t& l) {
    __nv_bfloat16 ah = __float2bfloat16(a), bh = __float2bfloat16(b);
    __nv_bfloat16 al = __float2bfloat16(a - __bfloat162float(ah));
    __nv_bfloat16 bl = __float2bfloat16(b - __bfloat162float(bh));
    h = (uint32_t)__bfloat16_as_ushort(ah) | ((uint32_t)__bfloat16_as_ushort(bh) << 16);
    l = (uint32_t)__bfloat16_as_ushort(al) | ((uint32_t)__bfloat16_as_ushort(bl) << 16);
}
__device__ __forceinline__ float gelu1(float x) {
    float t = tanhf(0.7978845608028654f * (x + 0.044715f * x * x * x));
    return 0.5f * x * (1.f + t);
}

// 128x128x128 bf16 warp-mma, 3 or 4 passes (full=1 adds Al*Bl)
template <int FULL>
__device__ __forceinline__ void mma_block(float (&acc)[4][4][4],
                                          const __nv_bfloat16* Ah, const __nv_bfloat16* Al,
                                          const __nv_bfloat16* Bh, const __nv_bfloat16* Bl,
                                          int mrowb, int ncolb, int lane) {
    int r_l = lane >> 2, c_l = (lane & 3) * 2;
#pragma unroll
    for (int ks = 0; ks < 8; ks++) {
        int kc = ks * 16;
        uint32_t a[4][4], b[4][2], b2[4][2];
#pragma unroll
        for (int mt = 0; mt < 4; mt++) {
            int r = mrowb + mt * 16 + r_l;
            a[mt][0] = *(const uint32_t*)(Ah + r * SA + kc + c_l);
            a[mt][1] = *(const uint32_t*)(Ah + (r + 8) * SA + kc + c_l);
            a[mt][2] = *(const uint32_t*)(Ah + r * SA + kc + c_l + 8);
            a[mt][3] = *(const uint32_t*)(Ah + (r + 8) * SA + kc + c_l + 8);
        }
#pragma unroll
        for (int ntl = 0; ntl < 4; ntl++) {
            int nn = ncolb + ntl * 8 + r_l;
            b[ntl][0] = *(const uint32_t*)(Bh + nn * SA + kc + c_l);
            b[ntl][1] = *(const uint32_t*)(Bh + nn * SA + kc + c_l + 8);
            b2[ntl][0] = *(const uint32_t*)(Bl + nn * SA + kc + c_l);
            b2[ntl][1] = *(const uint32_t*)(Bl + nn * SA + kc + c_l + 8);
        }
#pragma unroll
        for (int mt = 0; mt < 4; mt++)
#pragma unroll
            for (int ntl = 0; ntl < 4; ntl++) {
                MMA(acc[mt][ntl], a[mt], b[ntl]);
                MMA(acc[mt][ntl], a[mt], b2[ntl]);
            }
#pragma unroll
        for (int mt = 0; mt < 4; mt++) {
            int r = mrowb + mt * 16 + r_l;
            a[mt][0] = *(const uint32_t*)(Al + r * SA + kc + c_l);
            a[mt][1] = *(const uint32_t*)(Al + (r + 8) * SA + kc + c_l);
            a[mt][2] = *(const uint32_t*)(Al + r * SA + kc + c_l + 8);
            a[mt][3] = *(const uint32_t*)(Al + (r + 8) * SA + kc + c_l + 8);
        }
#pragma unroll
        for (int mt = 0; mt < 4; mt++)
#pragma unroll
            for (int ntl = 0; ntl < 4; ntl++) {
                MMA(acc[mt][ntl], a[mt], b[ntl]);
                if (FULL) MMA(acc[mt][ntl], a[mt], b2[ntl]);
            }
    }
}

// ---------------- scratch ----------------
__device__ float g_h[NTOK * DD];
__device__ float g_z[NTOK * DD];
__device__ float g_qkv[NTOK * 3 * DD];
__device__ float g_o[NTOK * DD];
__device__ float g_y[NASG * DD];
__device__ float g_blockSumP[512 * EE];
__device__ int   g_count[EE];
__device__ int   g_base[EE];
__device__ int   g_cursor[EE];
__device__ int   g_tok[NASG];
__device__ int   g_tope[NTOK * 2];
__device__ float g_topw[NTOK * 2];
__device__ int   g_pos[NTOK * 2];
__device__ float g_aux[1];
__device__ __nv_bfloat16 g_wqt_h[DEPTH_ * 384 * 128];
__device__ __nv_bfloat16 g_wqt_l[DEPTH_ * 384 * 128];
__device__ __nv_bfloat16 g_wot_h[DEPTH_ * 128 * 128];
__device__ __nv_bfloat16 g_wot_l[DEPTH_ * 128 * 128];
__device__ __nv_bfloat16 g_w1t_h[DEPTH_ * EE * 512 * 128];
__device__ __nv_bfloat16 g_w1t_l[DEPTH_ * EE * 512 * 128];
__device__ __nv_bfloat16 g_w2t_h[DEPTH_ * EE * 128 * 512];
__device__ __nv_bfloat16 g_w2t_l[DEPTH_ * EE * 128 * 512];
__device__ __nv_bfloat16 g_wpt_h[128 * KPJ];
__device__ __nv_bfloat16 g_wpt_l[128 * KPJ];
__device__ __nv_bfloat16 g_hid_h[(size_t)NASG * FFH];
__device__ __nv_bfloat16 g_hid_l[(size_t)NASG * FFH];

// transpose + split: src f32 [Z][R][C] -> dst bf16 [Z][C][R]
__global__ void k_tsplit(const float* __restrict__ src, int which, int R, int C) {
    __nv_bfloat16 *dh, *dl;
    if (which == 0)      { dh = g_wqt_h; dl = g_wqt_l; }
    else if (which == 1) { dh = g_wot_h; dl = g_wot_l; }
    else if (which == 2) { dh = g_w1t_h; dl = g_w1t_l; }
    else                 { dh = g_w2t_h; dl = g_w2t_l; }
    __shared__ float t[32][33];
    int z = blockIdx.z;
    int r0 = blockIdx.y * 32, c0 = blockIdx.x * 32;
    const float* s = src + (size_t)z * R * C;
    int tx = threadIdx.x & 31, ty = threadIdx.x >> 5;
#pragma unroll
    for (int i = 0; i < 32; i += 8) t[ty + i][tx] = s[(size_t)(r0 + ty + i) * C + c0 + tx];
    __syncthreads();
    __nv_bfloat16* ph = dh + (size_t)z * R * C;
    __nv_bfloat16* pl = dl + (size_t)z * R * C;
#pragma unroll
    for (int i = 0; i < 32; i += 8) {
        int c = c0 + ty + i, r = r0 + tx;
        float v = t[tx][ty + i];
        __nv_bfloat16 h = __float2bfloat16(v);
        ph[(size_t)c * R + r] = h;
        pl[(size_t)c * R + r] = __float2bfloat16(v - __bfloat162float(h));
    }
}

// proj weight: src f32 [INJ][128] -> dst bf16 [128][KPJ] zero-padded
__global__ void k_tsplit_proj(const float* __restrict__ src) {
    __shared__ float t[32][33];
    int r0 = blockIdx.y * 32, c0 = blockIdx.x * 32;
    int tx = threadIdx.x & 31, ty = threadIdx.x >> 5;
#pragma unroll
    for (int i = 0; i < 32; i += 8) {
        int r = r0 + ty + i;
        t[ty + i][tx] = (r < INJ) ? src[(size_t)r * 128 + c0 + tx] : 0.f;
    }
    __syncthreads();
#pragma unroll
    for (int i = 0; i < 32; i += 8) {
        int c = c0 + ty + i, r = r0 + tx;
        float v = t[tx][ty + i];
        __nv_bfloat16 h = __float2bfloat16(v);
        g_wpt_h[(size_t)c * KPJ + r] = h;
        g_wpt_l[(size_t)c * KPJ + r] = __float2bfloat16(v - __bfloat162float(h));
    }
}

// ---------------- MMA qkv: A loaded once from g_z, loop over 3 N-tiles ----------------
__global__ __launch_bounds__(256, 1) void k_mma_qkv(int li, const float* __restrict__ bias) {
    int t0 = blockIdx.x * 128;
    extern __shared__ __nv_bfloat16 smbf[];
    __nv_bfloat16* sAh = smbf;
    __nv_bfloat16* sAl = smbf + 128 * SA;
    __nv_bfloat16* sBh = smbf + 2 * 128 * SA;
    __nv_bfloat16* sBl = smbf + 3 * 128 * SA;
    int tid = threadIdx.x;
    for (int idx = tid; idx < 4096; idx += 256) {
        int r = idx >> 5, q = (idx & 31) << 2;
        float4 v = *(const float4*)(g_z + (size_t)(t0 + r) * 128 + q);
        PK4 ph, pl; split4(v, ph, pl);
        *(uint64_t*)(sAh + r * SA + q) = ph.u;
        *(uint64_t*)(sAl + r * SA + q) = pl.u;
    }
    int lane = tid & 31, wid = tid >> 5;
    int mrowb = (wid >> 2) * 64, ncolb = (wid & 3) * 32;
    int r_l = lane >> 2, c_l = (lane & 3) * 2;
#pragma unroll 1
    for (int nt = 0; nt < 3; nt++) {
        const __nv_bfloat16* bh = g_wqt_h + (size_t)li * 384 * 128 + (size_t)(nt * 128) * 128;
        const __nv_bfloat16* bl = g_wqt_l + (size_t)li * 384 * 128 + (size_t)(nt * 128) * 128;
        for (int idx = tid; idx < 4096; idx += 256) {
            int r = idx >> 5, q = (idx & 31) << 2;
            *(uint64_t*)(sBh + r * SA + q) = *(const uint64_t*)(bh + (size_t)r * 128 + q);
            *(uint64_t*)(sBl + r * SA + q) = *(const uint64_t*)(bl + (size_t)r * 128 + q);
        }
        __syncthreads();
        float acc[4][4][4] = {};
        mma_block<1>(acc, sAh, sAl, sBh, sBl, mrowb, ncolb, lane);
        __syncthreads();
        const float* bp = bias + nt * 128;
#pragma unroll
        for (int mt = 0; mt < 4; mt++)
#pragma unroll
            for (int ntl = 0; ntl < 4; ntl++) {
                int row = t0 + mrowb + mt * 16 + r_l;
                int c = ncolb + ntl * 8 + c_l;
                float b0 = bp[c], b1v = bp[c + 1];
                *(float2*)(g_qkv + (size_t)row * 384 + nt * 128 + c) =
                    make_float2(acc[mt][ntl][0] + b0, acc[mt][ntl][1] + b1v);
                *(float2*)(g_qkv + (size_t)(row + 8) * 384 + nt * 128 + c) =
                    make_float2(acc[mt][ntl][2] + b0, acc[mt][ntl][3] + b1v);
            }
    }
}

// ---------------- MMA out-proj + residual ----------------
__global__ __launch_bounds__(256, 1) void k_mma_out(int li, const float* __restrict__ bias) {
    int t0 = blockIdx.x * 128;
    extern __shared__ __nv_bfloat16 smbf[];
    __nv_bfloat16* sAh = smbf;
    __nv_bfloat16* sAl = smbf + 128 * SA;
    __nv_bfloat16* sBh = smbf + 2 * 128 * SA;
    __nv_bfloat16* sBl = smbf + 3 * 128 * SA;
    int tid = threadIdx.x;
    for (int idx = tid; idx < 4096; idx += 256) {
        int r = idx >> 5, q = (idx & 31) << 2;
        float4 v = *(const float4*)(g_o + (size_t)(t0 + r) * 128 + q);
        PK4 ph, pl; split4(v, ph, pl);
        *(uint64_t*)(sAh + r * SA + q) = ph.u;
        *(uint64_t*)(sAl + r * SA + q) = pl.u;
    }
    {
        const __nv_bfloat16* bh = g_wot_h + (size_t)li * 128 * 128;
        const __nv_bfloat16* bl = g_wot_l + (size_t)li * 128 * 128;
        for (int idx = tid; idx < 4096; idx += 256) {
            int r = idx >> 5, q = (idx & 31) << 2;
            *(uint64_t*)(sBh + r * SA + q) = *(const uint64_t*)(bh + (size_t)r * 128 + q);
            *(uint64_t*)(sBl + r * SA + q) = *(const uint64_t*)(bl + (size_t)r * 128 + q);
        }
    }
    __syncthreads();
    int lane = tid & 31, wid = tid >> 5;
    int mrowb = (wid >> 2) * 64, ncolb = (wid & 3) * 32;
    float acc[4][4][4] = {};
    mma_block<1>(acc, sAh, sAl, sBh, sBl, mrowb, ncolb, lane);
    int r_l = lane >> 2, c_l = (lane & 3) * 2;
#pragma unroll
    for (int mt = 0; mt < 4; mt++)
#pragma unroll
        for (int ntl = 0; ntl < 4; ntl++) {
            int row = t0 + mrowb + mt * 16 + r_l;
            int c = ncolb + ntl * 8 + c_l;
            float b0 = bias[c], b1v = bias[c + 1];
            float2* p0 = (float2*)(g_h + (size_t)row * 128 + c);
            float2* p1 = (float2*)(g_h + (size_t)(row + 8) * 128 + c);
            float2 h0 = *p0, h1 = *p1;
            *p0 = make_float2(h0.x + acc[mt][ntl][0] + b0, h0.y + acc[mt][ntl][1] + b1v);
            *p1 = make_float2(h1.x + acc[mt][ntl][2] + b0, h1.y + acc[mt][ntl][3] + b1v);
        }
}

// ---------------- MMA input projection ----------------
__global__ __launch_bounds__(256, 1) void k_mma_proj(const float* __restrict__ x,
                                                     const float* __restrict__ bias,
                                                     const float* __restrict__ pos) {
    int t0 = blockIdx.x * 128;
    extern __shared__ __nv_bfloat16 smbf[];
    __nv_bfloat16* sAh = smbf;
    __nv_bfloat16* sAl = smbf + 128 * SA;
    __nv_bfloat16* sBh = smbf + 2 * 128 * SA;
    __nv_bfloat16* sBl = smbf + 3 * 128 * SA;
    int tid = threadIdx.x;
    int lane = tid & 31, wid = tid >> 5;
    int mrowb = (wid >> 2) * 64, ncolb = (wid & 3) * 32;
    float acc[4][4][4] = {};
#pragma unroll 1
    for (int kt = 0; kt < 4; kt++) {
        for (int idx = tid; idx < 4096; idx += 256) {
            int r = idx >> 5, q = (idx & 31) << 2;
            int tok = t0 + r;
            int b = tok >> 9, t = tok & 511;
            float4 v;
            int j0 = kt * 128 + q;
#pragma unroll
            for (int c = 0; c < 4; c++) {
                int j = j0 + c;
                float val = 0.f;
                if (j < INJ) val = x[(((size_t)(b * NBC + j / NCC) * TT + t) * NCC) + (j % NCC)];
                ((float*)&v)[c] = val;
            }
            PK4 ph, pl; split4(v, ph, pl);
            *(uint64_t*)(sAh + r * SA + q) = ph.u;
            *(uint64_t*)(sAl + r * SA + q) = pl.u;
        }
        for (int idx = tid; idx < 4096; idx += 256) {
            int r = idx >> 5, q = (idx & 31) << 2;
            *(uint64_t*)(sBh + r * SA + q) = *(const uint64_t*)(g_wpt_h + (size_t)r * KPJ + kt * 128 + q);
            *(uint64_t*)(sBl + r * SA + q) = *(const uint64_t*)(g_wpt_l + (size_t)r * KPJ + kt * 128 + q);
        }
        __syncthreads();
        mma_block<1>(acc, sAh, sAl, sBh, sBl, mrowb, ncolb, lane);
        __syncthreads();
    }
    int r_l = lane >> 2, c_l = (lane & 3) * 2;
#pragma unroll
    for (int mt = 0; mt < 4; mt++)
#pragma unroll
        for (int ntl = 0; ntl < 4; ntl++) {
            int row = t0 + mrowb + mt * 16 + r_l;
            int c = ncolb + ntl * 8 + c_l;
            float b0 = bias[c], b1v = bias[c + 1];
            int ta = row & 511, tb = (row + 8) & 511;
            float2 pA = *(const float2*)(pos + (size_t)ta * 128 + c);
            float2 pB = *(const float2*)(pos + (size_t)tb * 128 + c);
            *(float2*)(g_h + (size_t)row * 128 + c) =
                make_float2(acc[mt][ntl][0] + b0 + pA.x, acc[mt][ntl][1] + b1v + pA.y);
            *(float2*)(g_h + (size_t)(row + 8) * 128 + c) =
                make_float2(acc[mt][ntl][2] + b0 + pB.x, acc[mt][ntl][3] + b1v + pB.y);
        }
}

// ---------------- FFN GEMM1 + gelu: A gathered once, loop over 4 f-tiles, 3-pass ----------------
__global__ __launch_bounds__(256, 1) void k_ffn1(int li, const float* __restrict__ b1) {
    int e = blockIdx.y;
    int n = g_count[e];
    int start = blockIdx.x * 128;
    if (start >= n) return;
    int base = g_base[e];
    extern __shared__ __nv_bfloat16 smbf[];
    __nv_bfloat16* sAh = smbf;
    __nv_bfloat16* sAl = smbf + 128 * SA;
    __nv_bfloat16* sBh = smbf + 2 * 128 * SA;
    __nv_bfloat16* sBl = smbf + 3 * 128 * SA;
    __shared__ int toks[128];
    int tid = threadIdx.x;
    if (tid < 128) toks[tid] = (start + tid < n) ? g_tok[base + start + tid] : -1;
    __syncthreads();
    for (int idx = tid; idx < 4096; idx += 256) {
        int r = idx >> 5, q = (idx & 31) << 2;
        int tk = toks[r];
        float4 v = make_float4(0.f, 0.f, 0.f, 0.f);
        if (tk >= 0) v = *(const float4*)(g_z + (size_t)tk * 128 + q);
        PK4 ph, pl; split4(v, ph, pl);
        *(uint64_t*)(sAh + r * SA + q) = ph.u;
        *(uint64_t*)(sAl + r * SA + q) = pl.u;
    }
    int lane = tid & 31, wid = tid >> 5;
    int mrowb = (wid >> 2) * 64, ncolb = (wid & 3) * 32;
    int r_l = lane >> 2, c_l = (lane & 3) * 2;
    const __nv_bfloat16* W1h = g_w1t_h + (size_t)(li * EE + e) * 512 * 128;
    const __nv_bfloat16* W1l = g_w1t_l + (size_t)(li * EE + e) * 512 * 128;
#pragma unroll 1
    for (int nt = 0; nt < 4; nt++) {
        const __nv_bfloat16* bh = W1h + (size_t)(nt * 128) * 128;
        const __nv_bfloat16* bl = W1l + (size_t)(nt * 128) * 128;
        for (int idx = tid; idx < 4096; idx += 256) {
            int r = idx >> 5, q = (idx & 31) << 2;
            *(uint64_t*)(sBh + r * SA + q) = *(const uint64_t*)(bh + (size_t)r * 128 + q);
            *(uint64_t*)(sBl + r * SA + q) = *(const uint64_t*)(bl + (size_t)r * 128 + q);
        }
        __syncthreads();
        float acc[4][4][4] = {};
        mma_block<0>(acc, sAh, sAl, sBh, sBl, mrowb, ncolb, lane);
        __syncthreads();
        const float* b1p = b1 + e * FFH + nt * 128;
#pragma unroll
        for (int mt = 0; mt < 4; mt++)
#pragma unroll
            for (int ntl = 0; ntl < 4; ntl++) {
                int rloc = mrowb + mt * 16 + r_l;
                int f = ncolb + ntl * 8 + c_l;
                float bb0 = b1p[f], bb1 = b1p[f + 1];
                uint32_t h, l;
                if (start + rloc < n) {
                    float v0 = gelu1(acc[mt][ntl][0] + bb0);
                    float v1 = gelu1(acc[mt][ntl][1] + bb1);
                    pksplit2(v0, v1, h, l);
                    size_t o = (size_t)(base + start + rloc) * FFH + nt * 128 + f;
                    *(uint32_t*)(g_hid_h + o) = h;
                    *(uint32_t*)(g_hid_l + o) = l;
                }
                if (start + rloc + 8 < n) {
                    float v2 = gelu1(acc[mt][ntl][2] + bb0);
                    float v3 = gelu1(acc[mt][ntl][3] + bb1);
                    pksplit2(v2, v3, h, l);
                    size_t o = (size_t)(base + start + rloc + 8) * FFH + nt * 128 + f;
                    *(uint32_t*)(g_hid_h + o) = h;
                    *(uint32_t*)(g_hid_l + o) = l;
                }
            }
    }
}

// ---------------- FFN GEMM2 (3-pass) ----------------
__global__ __launch_bounds__(256, 1) void k_ffn2(int li, const float* __restrict__ b2) {
    int e = blockIdx.y;
    int n = g_count[e];
    int start = blockIdx.x * 128;
    if (start >= n) return;
    int base = g_base[e];
    extern __shared__ __nv_bfloat16 smbf[];
    __nv_bfloat16* sAh = smbf;
    __nv_bfloat16* sAl = smbf + 128 * SA;
    __nv_bfloat16* sBh = smbf + 2 * 128 * SA;
    __nv_bfloat16* sBl = smbf + 3 * 128 * SA;
    int tid = threadIdx.x;
    int lane = tid & 31, wid = tid >> 5;
    int mrowb = (wid >> 2) * 64, ncolb = (wid & 3) * 32;
    float acc[4][4][4] = {};
    const __nv_bfloat16* W2h = g_w2t_h + (size_t)(li * EE + e) * 128 * 512;
    const __nv_bfloat16* W2l = g_w2t_l + (size_t)(li * EE + e) * 128 * 512;
#pragma unroll 1
    for (int kt = 0; kt < 4; kt++) {
        for (int idx = tid; idx < 4096; idx += 256) {
            int r = idx >> 5, q = (idx & 31) << 2;
            uint64_t vh = 0, vl = 0;
            if (start + r < n) {
                size_t o = (size_t)(base + start + r) * FFH + kt * 128 + q;
                vh = *(const uint64_t*)(g_hid_h + o);
                vl = *(const uint64_t*)(g_hid_l + o);
            }
            *(uint64_t*)(sAh + r * SA + q) = vh;
            *(uint64_t*)(sAl + r * SA + q) = vl;
        }
        for (int idx = tid; idx < 4096; idx += 256) {
            int r = idx >> 5, q = (idx & 31) << 2;
            *(uint64_t*)(sBh + r * SA + q) = *(const uint64_t*)(W2h + (size_t)r * 512 + kt * 128 + q);
            *(uint64_t*)(sBl + r * SA + q) = *(const uint64_t*)(W2l + (size_t)r * 512 + kt * 128 + q);
        }
        __syncthreads();
        mma_block<0>(acc, sAh, sAl, sBh, sBl, mrowb, ncolb, lane);
        __syncthreads();
    }
    const float* b2p = b2 + e * DD;
    int r_l = lane >> 2, c_l = (lane & 3) * 2;
#pragma unroll
    for (int mt = 0; mt < 4; mt++)
#pragma unroll
        for (int ntl = 0; ntl < 4; ntl++) {
            int rloc = mrowb + mt * 16 + r_l;
            int col = ncolb + ntl * 8 + c_l;
            float b0 = b2p[col], b1v = b2p[col + 1];
            if (start + rloc < n)
                *(float2*)(g_y + (size_t)(base + start + rloc) * DD + col) =
                    make_float2(acc[mt][ntl][0] + b0, acc[mt][ntl][1] + b1v);
            if (start + rloc + 8 < n)
                *(float2*)(g_y + (size_t)(base + start + rloc + 8) * DD + col) =
                    make_float2(acc[mt][ntl][2] + b0, acc[mt][ntl][3] + b1v);
        }
}

// ---------------- LayerNorm (zg=1 also zeroes gate counters from block 0) ----------------
__global__ void k_ln(const float* __restrict__ gam, const float* __restrict__ bet, int zg) {
    if (zg && blockIdx.x == 0 && threadIdx.x < EE) g_count[threadIdx.x] = 0;
    int warp = (blockIdx.x * blockDim.x + threadIdx.x) >> 5;
    int lane = threadIdx.x & 31;
    if (warp >= NTOK) return;
    const float* xr = g_h + warp * DD;
    float v[4];
    float s = 0.f;
#pragma unroll
    for (int j = 0; j < 4; j++) { v[j] = xr[lane + j * 32]; s += v[j]; }
#pragma unroll
    for (int o = 16; o; o >>= 1) s += __shfl_xor_sync(0xffffffffu, s, o);
    float m = s * (1.0f / DD);
    float q = 0.f;
#pragma unroll
    for (int j = 0; j < 4; j++) { float dv = v[j] - m; q += dv * dv; }
#pragma unroll
    for (int o = 16; o; o >>= 1) q += __shfl_xor_sync(0xffffffffu, q, o);
    float r = rsqrtf(q * (1.0f / DD) + 1e-5f);
#pragma unroll
    for (int j = 0; j < 4; j++) {
        int d = lane + j * 32;
        g_z[warp * DD + d] = (v[j] - m) * r * gam[d] + bet[d];
    }
}

// ---------------- attention (monolithic, round-13 verified) ----------------
__global__ __launch_bounds__(256) void k_attn() {
    extern __shared__ float sm[];
    float* Ks = sm;
    float* Vs = sm + TT * DHH;
    int b = blockIdx.x >> 3, hh = blockIdx.x & 7;
    const float* base = g_qkv + (b * TT) * 384;
    for (int idx = threadIdx.x; idx < TT * DHH; idx += 256) {
        int k = idx >> 4, d = idx & 15;
        Ks[idx] = base[k * 384 + 128 + hh * 16 + d];
        Vs[idx] = base[k * 384 + 256 + hh * 16 + d];
    }
    __syncthreads();
    int r0 = threadIdx.x, r1 = threadIdx.x + 256;
    u64 q0[8], q1[8], o0[8] = {}, o1[8] = {};
    {
        const ulonglong2* qp0 = (const ulonglong2*)(base + r0 * 384 + hh * 16);
        const ulonglong2* qp1 = (const ulonglong2*)(base + r1 * 384 + hh * 16);
        u64 sc = pk2(0.25f);
#pragma unroll
        for (int j = 0; j < 4; j++) {
            ulonglong2 t = qp0[j];
            q0[2 * j] = mul2(t.x, sc); q0[2 * j + 1] = mul2(t.y, sc);
            t = qp1[j];
            q1[2 * j] = mul2(t.x, sc); q1[2 * j + 1] = mul2(t.y, sc);
        }
    }
    float m0 = -1e30f, l0 = 0.f, m1 = -1e30f, l1 = 0.f;
#pragma unroll 1
    for (int k = 0; k < TT; k++) {
        const ulonglong2* kp = (const ulonglong2*)(Ks + k * 16);
        u64 kk[8];
#pragma unroll
        for (int j = 0; j < 4; j++) { ulonglong2 t = kp[j]; kk[2 * j] = t.x; kk[2 * j + 1] = t.y; }
        u64 sa = mul2(q0[0], kk[0]), sb = mul2(q0[1], kk[1]);
        sa = fma2(q0[2], kk[2], sa); sb = fma2(q0[3], kk[3], sb);
        sa = fma2(q0[4], kk[4], sa); sb = fma2(q0[5], kk[5], sb);
        sa = fma2(q0[6], kk[6], sa); sb = fma2(q0[7], kk[7], sb);
        float2 sr = up2(add2(sa, sb));
        float s0v = sr.x + sr.y;
        sa = mul2(q1[0], kk[0]); sb = mul2(q1[1], kk[1]);
        sa = fma2(q1[2], kk[2], sa); sb = fma2(q1[3], kk[3], sb);
        sa = fma2(q1[4], kk[4], sa); sb = fma2(q1[5], kk[5], sb);
        sa = fma2(q1[6], kk[6], sa); sb = fma2(q1[7], kk[7], sb);
        sr = up2(add2(sa, sb));
        float s1v = sr.x + sr.y;
        const ulonglong2* vp = (const ulonglong2*)(Vs + k * 16);
        u64 vv[8];
#pragma unroll
        for (int j = 0; j < 4; j++) { ulonglong2 t = vp[j]; vv[2 * j] = t.x; vv[2 * j + 1] = t.y; }
        if (s0v > m0) {
            float f = __expf(m0 - s0v);
            l0 *= f;
            u64 fp = pk2(f);
#pragma unroll
            for (int j = 0; j < 8; j++) o0[j] = mul2(o0[j], fp);
            m0 = s0v;
        }
        float p0 = __expf(s0v - m0);
        l0 += p0;
        u64 pp0 = pk2(p0);
#pragma unroll
        for (int j = 0; j < 8; j++) o0[j] = fma2(pp0, vv[j], o0[j]);
        if (s1v > m1) {
            float f = __expf(m1 - s1v);
            l1 *= f;
            u64 fp = pk2(f);
#pragma unroll
            for (int j = 0; j < 8; j++) o1[j] = mul2(o1[j], fp);
            m1 = s1v;
        }
        float p1 = __expf(s1v - m1);
        l1 += p1;
        u64 pp1 = pk2(p1);
#pragma unroll
        for (int j = 0; j < 8; j++) o1[j] = fma2(pp1, vv[j], o1[j]);
    }
    float inv0 = 1.f / l0, inv1 = 1.f / l1;
    float4* op0 = (float4*)(g_o + (b * TT + r0) * DD + hh * 16);
    float4* op1 = (float4*)(g_o + (b * TT + r1) * DD + hh * 16);
#pragma unroll
    for (int j = 0; j < 4; j++) {
        float2 a = up2(o0[2 * j]), c = up2(o0[2 * j + 1]);
        op0[j] = make_float4(a.x * inv0, a.y * inv0, c.x * inv0, c.y * inv0);
        a = up2(o1[2 * j]); c = up2(o1[2 * j + 1]);
        op1[j] = make_float4(a.x * inv1, a.y * inv1, c.x * inv1, c.y * inv1);
    }
}

// ---------------- gate / scan / assign / combine / head ----------------
__global__ void k_gate(const float* __restrict__ gW) {
    __shared__ float zs[32 * DD];
    __shared__ float gw[DD * EE];
    __shared__ float lg[32 * EE];
    __shared__ float sp[32 * EE];
    int t0 = blockIdx.x * 32;
    for (int idx = threadIdx.x; idx < 32 * DD; idx += 256) zs[idx] = g_z[t0 * DD + idx];
    for (int idx = threadIdx.x; idx < DD * EE; idx += 256) gw[idx] = gW[idx];
    __syncthreads();
    {
        int tok = threadIdx.x >> 3, e = threadIdx.x & 7;
        float acc = 0.f;
        for (int k = 0; k < DD; k++) acc += zs[tok * DD + k] * gw[k * EE + e];
        lg[tok * EE + e] = acc;
    }
    __syncthreads();
    if (threadIdx.x < 32) {
        int tt = threadIdx.x;
        float mx = -1e30f;
#pragma unroll
        for (int j = 0; j < 8; j++) mx = fmaxf(mx, lg[tt * 8 + j]);
        float p[8];
        float s = 0.f;
#pragma unroll
        for (int j = 0; j < 8; j++) { p[j] = __expf(lg[tt * 8 + j] - mx); s += p[j]; }
        float invs = 1.f / s;
#pragma unroll
        for (int j = 0; j < 8; j++) p[j] *= invs;
        int i1 = 0; float l1 = lg[tt * 8];
        for (int j = 1; j < 8; j++) if (lg[tt * 8 + j] > l1) { l1 = lg[tt * 8 + j]; i1 = j; }
        int i2 = -1; float l2 = -1e30f;
        for (int j = 0; j < 8; j++)
            if (j != i1 && lg[tt * 8 + j] > l2) { l2 = lg[tt * 8 + j]; i2 = j; }
        float v1 = p[i1], v2 = p[i2];
        float ws = 1.f / (v1 + v2);
        int t = t0 + tt;
        g_tope[t * 2] = i1; g_tope[t * 2 + 1] = i2;
        g_topw[t * 2] = v1 * ws; g_topw[t * 2 + 1] = v2 * ws;
        atomicAdd(&g_count[i1], 1);
        atomicAdd(&g_count[i2], 1);
#pragma unroll
        for (int j = 0; j < 8; j++) sp[tt * 8 + j] = p[j];
    }
    __syncthreads();
    if (threadIdx.x < 8) {
        float s = 0.f;
        for (int tt = 0; tt < 32; tt++) s += sp[tt * 8 + threadIdx.x];
        g_blockSumP[blockIdx.x * 8 + threadIdx.x] = s;
    }
}

__global__ void k_scan_aux() {
    __shared__ float sump[8];
    int tid = threadIdx.x;
    if (tid < 8) {
        float s = 0.f;
        for (int b = 0; b < 512; b++) s += g_blockSumP[b * 8 + tid];
        sump[tid] = s;
    }
    __syncthreads();
    if (tid == 0) {
        int off = 0;
        float a = 0.f;
        for (int e = 0; e < 8; e++) {
            g_base[e] = off;
            g_cursor[e] = off;
            off += g_count[e];
            a += sump[e] * (float)g_count[e];
        }
        g_aux[0] += 8.0f * a / (16384.f * 16384.f);
    }
}

__global__ void k_assign() {
    __shared__ int cnt[8], gbase[8];
    int tid = threadIdx.x;
    if (tid < 8) cnt[tid] = 0;
    __syncthreads();
    int t = blockIdx.x * 256 + tid;
    int e0 = g_tope[t * 2], e1 = g_tope[t * 2 + 1];
    int o0 = atomicAdd(&cnt[e0], 1);
    int o1 = atomicAdd(&cnt[e1], 1);
    __syncthreads();
    if (tid < 8) gbase[tid] = atomicAdd(&g_cursor[tid], cnt[tid]);
    __syncthreads();
    int p0 = gbase[e0] + o0, p1 = gbase[e1] + o1;
    g_tok[p0] = t; g_tok[p1] = t;
    g_pos[t * 2] = p0; g_pos[t * 2 + 1] = p1;
}

// combine, float4: h += w0*y[pos0] + w1*y[pos1]
__global__ void k_combine() {
    int idx = blockIdx.x * 256 + threadIdx.x;   // over NTOK*32
    int t = idx >> 5, d = (idx & 31) << 2;
    float w0 = g_topw[t * 2], w1v = g_topw[t * 2 + 1];
    int p0 = g_pos[t * 2], p1 = g_pos[t * 2 + 1];
    float4 a = *(const float4*)(g_y + (size_t)p0 * DD + d);
    float4 b = *(const float4*)(g_y + (size_t)p1 * DD + d);
    float4* hp = (float4*)(g_h + (size_t)t * DD + d);
    float4 h = *hp;
    *hp = make_float4(h.x + w0 * a.x + w1v * b.x, h.y + w0 * a.y + w1v * b.y,
                      h.z + w0 * a.z + w1v * b.z, h.w + w0 * a.w + w1v * b.w);
}

__global__ void k_head(const float* __restrict__ lng, const float* __restrict__ lnb,
                       const float* __restrict__ hW, const float* __restrict__ hb,
                       float* __restrict__ out, int out_size) {
    __shared__ float red[128];
    int b = blockIdx.x, d = threadIdx.x;
    float s = 0.f;
    for (int t = 0; t < TT; t++) s += g_h[(b * TT + t) * DD + d];
    float x = s * (1.f / TT);
    red[d] = x;
    __syncthreads();
    for (int o = 64; o; o >>= 1) { if (d < o) red[d] += red[d + o]; __syncthreads(); }
    float m = red[0] * (1.f / DD);
    __syncthreads();
    float dv = x - m;
    red[d] = dv * dv;
    __syncthreads();
    for (int o = 64; o; o >>= 1) { if (d < o) red[d] += red[d + o]; __syncthreads(); }
    float var = red[0] * (1.f / DD);
    __syncthreads();
    float p = dv * rsqrtf(var + 1e-5f) * lng[d] + lnb[d];
#pragma unroll 1
    for (int j = 0; j < 2; j++) {
        red[d] = p * hW[d * 2 + j];
        __syncthreads();
        for (int o = 64; o; o >>= 1) { if (d < o) red[d] += red[d + o]; __syncthreads(); }
        if (d == 0) out[b * 2 + j] = red[0] + hb[j];
        __syncthreads();
    }
    if (b == 0 && d == 0 && out_size > 64) out[64] = g_aux[0];
}

__global__ void k_zero_aux() { if (threadIdx.x == 0) g_aux[0] = 0.f; }

// ---------------- host launch ----------------
extern "C" void kernel_launch(void* const* d_in, const int* in_sizes, int n_in,
                              void* d_out, int out_size) {
    const float* x     = (const float*)d_in[0];
    const float* projW = (const float*)d_in[1];
    const float* projb = (const float*)d_in[2];
    const float* pos   = (const float*)d_in[3];
    const float* ln1g  = (const float*)d_in[4];
    const float* ln1b  = (const float*)d_in[5];
    const float* qkvW  = (const float*)d_in[6];
    const float* qkvb  = (const float*)d_in[7];
    const float* outW  = (const float*)d_in[8];
    const float* outb  = (const float*)d_in[9];
    const float* ln2g  = (const float*)d_in[10];
    const float* ln2b  = (const float*)d_in[11];
    const float* gateW = (const float*)d_in[12];
    const float* w1    = (const float*)d_in[13];
    const float* b1    = (const float*)d_in[14];
    const float* w2    = (const float*)d_in[15];
    const float* b2    = (const float*)d_in[16];
    const float* hlng  = (const float*)d_in[17];
    const float* hlnb  = (const float*)d_in[18];
    const float* hW    = (const float*)d_in[19];
    const float* hb    = (const float*)d_in[20];
    float* out = (float*)d_out;

    const int FFNS = 4 * 128 * SA * 2;   // 139264

    cudaFuncSetAttribute(k_attn, cudaFuncAttributeMaxDynamicSharedMemorySize, 65536);
    cudaFuncSetAttribute(k_ffn1, cudaFuncAttributeMaxDynamicSharedMemorySize, FFNS);
    cudaFuncSetAttribute(k_ffn2, cudaFuncAttributeMaxDynamicSharedMemorySize, FFNS);
    cudaFuncSetAttribute(k_mma_qkv, cudaFuncAttributeMaxDynamicSharedMemorySize, FFNS);
    cudaFuncSetAttribute(k_mma_out, cudaFuncAttributeMaxDynamicSharedMemorySize, FFNS);
    cudaFuncSetAttribute(k_mma_proj, cudaFuncAttributeMaxDynamicSharedMemorySize, FFNS);

    k_zero_aux<<<1, 32>>>();
    k_tsplit<<<dim3(12, 4, 4), 256>>>(qkvW, 0, 128, 384);
    k_tsplit<<<dim3(4, 4, 4), 256>>>(outW, 1, 128, 128);
    k_tsplit<<<dim3(16, 4, 32), 256>>>(w1, 2, 128, 512);
    k_tsplit<<<dim3(4, 16, 32), 256>>>(w2, 3, 512, 128);
    k_tsplit_proj<<<dim3(4, 14), 256>>>(projW);
    k_mma_proj<<<NTOK / 128, 256, FFNS>>>(x, projb, pos);

    for (int i = 0; i < DEPTH_; i++) {
        k_ln<<<NTOK / 8, 256>>>(ln1g + i * DD, ln1b + i * DD, 0);
        k_mma_qkv<<<NTOK / 128, 256, FFNS>>>(i, qkvb + i * 384);
        k_attn<<<BB * HH, 256, 65536>>>();
        k_mma_out<<<NTOK / 128, 256, FFNS>>>(i, outb + i * DD);
        k_ln<<<NTOK / 8, 256>>>(ln2g + i * DD, ln2b + i * DD, 1);
        k_gate<<<NTOK / 32, 256>>>(gateW + i * DD * EE);
        k_scan_aux<<<1, 32>>>();
        k_assign<<<NTOK / 256, 256>>>();
        k_ffn1<<<dim3(128, EE), 256, FFNS>>>(i, b1 + i * EE * FFH);
        k_ffn2<<<dim3(128, EE), 256, FFNS>>>(i, b2 + i * EE * DD);
        k_combine<<<NTOK * 32 / 256, 256>>>();
    }

    k_head<<<BB, 128>>>(hlng, hlnb, hW, hb, out, out_size);
}